// round 13
// baseline (speedup 1.0000x reference)
#include <cuda_runtime.h>
#include <cuda_fp16.h>
#include <cstdint>

// ============================================================================
// BilinearChebConv via mma.sync, fully recursive plane construction.
// out[o] = sum_{i,j} theta[i,j,o] * (Tr_i @ X @ Tc_j) + bias[o]
// M = N = 1536, orders 4/4, OUT = 32.
// R13: never build Tr/Tc. All planes via Chebyshev recursion (1 GEMM each):
//   Y_{k+1} = 2 Lr @ Y_k - Y_{k-1}        (Y0 = X; B operand = Y_k^T)
//   W_{j+1} = 2 W_j @ Lc - W_{j-1}        (W0 = X; no transposes)
//   Z_{i,j+1} = 2 Z_{i,j} @ Lc - Z_{i,j-1} (Z_{i,0} = Y_i; batched over i)
// MMA units 36 -> 24. All 1-term (fp16-hi x fp16-hi, fp32 accum, exact fp32 D).
// ============================================================================

constexpr int NM   = 1536;
constexpr int N2   = NM * NM;
constexpr int OUTC = 32;

constexpr int BK     = 64;                  // k per stage (64 fp16 = 128B row)
constexpr int NKT    = NM / BK;             // 24
constexpr int PLANE  = 128 * 128;           // bytes per operand plane per stage
constexpr int STAGE1 = 2 * PLANE;           // Ah|Bh = 32 KB
constexpr unsigned SMEM_DYN1 = 3 * STAGE1;  // 96 KB

// ----------------------------------------------------------------------------
// Scratch (no cudaMalloc allowed -> __device__ globals)
__device__ float g_Y32[4][N2];          // Y_i = Tr_i @ X
__device__ float g_W32[4][N2];          // W_j = X @ Tc_j
__device__ float g_Z32[16][N2];         // Z_ij, idx (i-1)*4 + (j-1)
// fp16 hi operand planes
__device__ __half g_Xh[N2];             // X row-major (A for W chain)
__device__ __half g_XTh[N2];            // X^T (B for Y step 0)
__device__ __half g_Lrh[N2], g_Lch[N2];
__device__ __half g_Yh[4][N2];          // Y_i row-major (A for Z step 0)
__device__ __half g_YTh[3][N2];         // Y_i^T (B for Y steps 1..3)
__device__ __half g_Wh[3][N2];          // W_j row-major (A for W steps 1..3)
__device__ __half g_Zh[4][3][N2];       // Z_{i,j} (A for Z steps 1..3)

// ----------------------------------------------------------------------------
// PTX helpers (all baseline sm_80+ instructions)
// ----------------------------------------------------------------------------
__device__ __forceinline__ uint32_t smem_u32(const void* p) {
    uint32_t a;
    asm("{ .reg .u64 t; cvta.to.shared.u64 t, %1; cvt.u32.u64 %0, t; }"
        : "=r"(a) : "l"(p));
    return a;
}
__device__ __forceinline__ void cpa16(uint32_t s, const void* g) {
    asm volatile("cp.async.cg.shared.global [%0], [%1], 16;\n" :: "r"(s), "l"(g));
}
__device__ __forceinline__ void cp_commit() {
    asm volatile("cp.async.commit_group;\n" ::: "memory");
}
__device__ __forceinline__ void cp_wait2() {
    asm volatile("cp.async.wait_group 2;\n" ::: "memory");
}
__device__ __forceinline__ void ldsm4(uint32_t* r, uint32_t a) {
    asm volatile("ldmatrix.sync.aligned.m8n8.x4.shared.b16 {%0,%1,%2,%3}, [%4];"
                 : "=r"(r[0]), "=r"(r[1]), "=r"(r[2]), "=r"(r[3]) : "r"(a));
}
__device__ __forceinline__ void mma16816(float* c, const uint32_t* a,
                                         uint32_t b0, uint32_t b1) {
    asm volatile("mma.sync.aligned.m16n8k16.row.col.f32.f16.f16.f32 "
                 "{%0,%1,%2,%3}, {%4,%5,%6,%7}, {%8,%9}, {%0,%1,%2,%3};"
                 : "+f"(c[0]), "+f"(c[1]), "+f"(c[2]), "+f"(c[3])
                 : "r"(a[0]), "r"(a[1]), "r"(a[2]), "r"(a[3]), "r"(b0), "r"(b1));
}

extern __shared__ char dsm[];

// ----------------------------------------------------------------------------
// 1-term core GEMM: C(128x128) += Ah * Bh^T(stored NxK) over K=1536.
// Block = 512 threads, 16 warps of 32x32. acc[2][4][4] per thread.
// ----------------------------------------------------------------------------
__device__ __forceinline__ void gemm_main1(
    const __half* __restrict__ Ah, const __half* __restrict__ Bh,
    float (&acc)[2][4][4])
{
    const uint32_t sbase = smem_u32(dsm);
    const int tid = threadIdx.x, lane = tid & 31, wid = tid >> 5;
    const int wm = (wid & 3) * 32, wn = (wid >> 2) * 32;
    const int l15 = lane & 15, lhi = lane >> 4;
    const int bm = blockIdx.y * 128, bn = blockIdx.x * 128;
    const int lc = tid & 7, lr = tid >> 3;

    auto load_stage = [&](int st, int kc) {
        const uint32_t sb = sbase + st * STAGE1;
#pragma unroll
        for (int rr = 0; rr < 128; rr += 64) {
            const int r = lr + rr;
            const uint32_t off = (uint32_t)(r * 128) + (uint32_t)((lc ^ (r & 7)) << 4);
            const size_t ga = (size_t)(bm + r) * NM + kc + lc * 8;
            const size_t gb = (size_t)(bn + r) * NM + kc + lc * 8;
            cpa16(sb + 0 * PLANE + off, Ah + ga);
            cpa16(sb + 1 * PLANE + off, Bh + gb);
        }
    };

    load_stage(0, 0);      cp_commit();
    load_stage(1, BK);     cp_commit();
    load_stage(2, 2 * BK); cp_commit();

    for (int kt = 0; kt < NKT; ++kt) {
        cp_wait2();
        __syncthreads();
        const uint32_t sb = sbase + (kt % 3) * STAGE1;
#pragma unroll
        for (int kh = 0; kh < 4; ++kh) {
            uint32_t ahf[2][4];
            const int chunkL = (kh << 1) | lhi;
#pragma unroll
            for (int mt = 0; mt < 2; ++mt) {
                const int r = wm + mt * 16 + l15;
                const uint32_t off = (uint32_t)(r * 128) +
                                     (uint32_t)((chunkL ^ (r & 7)) << 4);
                ldsm4(ahf[mt], sb + 0 * PLANE + off);
            }
#pragma unroll
            for (int g = 0; g < 2; ++g) {
                uint32_t bh4[4];
                const int r = wn + g * 16 + l15;
                const uint32_t off = (uint32_t)(r * 128) +
                                     (uint32_t)((chunkL ^ (r & 7)) << 4);
                ldsm4(bh4, sb + 1 * PLANE + off);
#pragma unroll
                for (int mt = 0; mt < 2; ++mt)
#pragma unroll
                    for (int j = 0; j < 2; ++j)
                        mma16816(acc[mt][g * 2 + j], ahf[mt], bh4[j], bh4[j + 2]);
            }
        }
        __syncthreads();
        if (kt + 3 < NKT) load_stage(kt % 3, (kt + 3) * BK);
        cp_commit();
    }
}

// Recursion epilogue: C = (D ? 2*acc - D : acc); writes fp32 + optional fp16 hi.
__device__ __forceinline__ void epi_rec(float (&acc)[2][4][4],
                                        const float* __restrict__ D,
                                        float* __restrict__ C,
                                        __half* __restrict__ Ho)
{
    const int tid = threadIdx.x, lane = tid & 31, wid = tid >> 5;
    const int wm = (wid & 3) * 32, wn = (wid >> 2) * 32;
    const int bm = blockIdx.y * 128, bn = blockIdx.x * 128;
    const int l4 = lane >> 2, l2 = (lane & 3) * 2;
#pragma unroll
    for (int mt = 0; mt < 2; ++mt)
#pragma unroll
        for (int h = 0; h < 2; ++h) {
            const int row = bm + wm + mt * 16 + l4 + h * 8;
#pragma unroll
            for (int nt = 0; nt < 4; ++nt) {
                const int col = bn + wn + nt * 8 + l2;
                const size_t off = (size_t)row * NM + col;
                float vx = acc[mt][nt][2 * h];
                float vy = acc[mt][nt][2 * h + 1];
                if (D) {
                    float2 d = *(const float2*)(D + off);
                    vx = 2.f * vx - d.x;
                    vy = 2.f * vy - d.y;
                }
                *(float2*)(C + off) = make_float2(vx, vy);
                if (Ho) {
                    __half2 q;
                    q.x = __float2half_rn(vx);
                    q.y = __float2half_rn(vy);
                    *(__half2*)(Ho + off) = q;
                }
            }
        }
}

// ----------------------------------------------------------------------------
// Kernels
// ----------------------------------------------------------------------------

// Y chain, step s computes Y_{s+1} = (s==0 ? Lr@X : 2*Lr@Y_s - Y_{s-1}).
// A = Lr hi; B = X^T hi (s==0) else Y_s^T hi.
__global__ void __launch_bounds__(512)
k_y(const float* __restrict__ x, int s)
{
    const __half* Bh = (s == 0) ? g_XTh : g_YTh[s - 1];
    const float* D = (s == 0) ? nullptr : (s == 1 ? x : g_Y32[s - 2]);
    float acc[2][4][4] = {};
    gemm_main1(g_Lrh, Bh, acc);
    epi_rec(acc, D, g_Y32[s], g_Yh[s]);
}

// W chain, step s computes W_{s+1} = (s==0 ? X@Lc : 2*W_s@Lc - W_{s-1}).
// A = X hi (s==0) else W_s hi; B = Lc hi (symmetric).
__global__ void __launch_bounds__(512)
k_w(const float* __restrict__ x, int s)
{
    const __half* Ah = (s == 0) ? g_Xh : g_Wh[s - 1];
    const float* D = (s == 0) ? nullptr : (s == 1 ? x : g_W32[s - 2]);
    float acc[2][4][4] = {};
    gemm_main1(Ah, g_Lch, acc);
    epi_rec(acc, D, g_W32[s], (s < 3) ? g_Wh[s] : nullptr);
}

// Z chain, step s computes Z_{i,s+1}; batched over i = blockIdx.z + 1.
// Z_{i,1} = Y_i@Lc; Z_{i,s+1} = 2*Z_{i,s}@Lc - Z_{i,s-1}.
__global__ void __launch_bounds__(512)
k_z(int s)
{
    const int zi = blockIdx.z;                  // i-1
    const __half* Ah = (s == 0) ? g_Yh[zi] : g_Zh[zi][s - 1];
    const float* D = (s == 0) ? nullptr
                   : (s == 1 ? g_Y32[zi] : g_Z32[zi * 4 + s - 2]);
    float acc[2][4][4] = {};
    gemm_main1(Ah, g_Lch, acc);
    epi_rec(acc, D, g_Z32[zi * 4 + s], (s < 3) ? g_Zh[zi][s] : nullptr);
}

// ----------------------------------------------------------------------------
// fp32 -> fp16 hi conversion of inputs (z: 0=X, 1=Lr, 2=Lc)
__global__ void __launch_bounds__(256)
k_cvt(const float* __restrict__ x, const float* __restrict__ Lr,
      const float* __restrict__ Lc)
{
    const int zz = blockIdx.z;
    const float* s = (zz == 0) ? x : (zz == 1) ? Lr : Lc;
    __half* H = (zz == 0) ? g_Xh : (zz == 1) ? g_Lrh : g_Lch;
    const int i = (blockIdx.x * 256 + threadIdx.x) * 4;
    float4 v = *(const float4*)(s + i);
    __half2 p;
    p.x = __float2half_rn(v.x); p.y = __float2half_rn(v.y);
    *(__half2*)(H + i) = p;
    p.x = __float2half_rn(v.z); p.y = __float2half_rn(v.w);
    *(__half2*)(H + i + 2) = p;
}

// X^T hi
__global__ void __launch_bounds__(256)
k_cvtT(const float* __restrict__ X)
{
    __shared__ float t[32][33];
    const int tx = threadIdx.x, ty = threadIdx.y;
    const int n0 = blockIdx.x * 32, m0 = blockIdx.y * 32;
#pragma unroll
    for (int i = 0; i < 4; ++i)
        t[ty + 8 * i][tx] = X[(size_t)(m0 + ty + 8 * i) * NM + n0 + tx];
    __syncthreads();
#pragma unroll
    for (int i = 0; i < 4; ++i) {
        const int nl = ty + 8 * i;
        g_XTh[(size_t)(n0 + nl) * NM + m0 + tx] = __float2half_rn(t[tx][nl]);
    }
}

// Y_s^T hi from g_Y32[s] (for the next Y step's B operand)
__global__ void __launch_bounds__(256)
k_trY(int s)
{
    const float* S = g_Y32[s];
    __half* TH = g_YTh[s];
    __shared__ float t[32][33];
    const int tx = threadIdx.x, ty = threadIdx.y;
    const int n0 = blockIdx.x * 32, m0 = blockIdx.y * 32;
#pragma unroll
    for (int i = 0; i < 4; ++i)
        t[ty + 8 * i][tx] = S[(size_t)(m0 + ty + 8 * i) * NM + n0 + tx];
    __syncthreads();
#pragma unroll
    for (int i = 0; i < 4; ++i) {
        const int nl = ty + 8 * i;
        TH[(size_t)(n0 + nl) * NM + m0 + tx] = __float2half_rn(t[tx][nl]);
    }
}

// ----------------------------------------------------------------------------
// Final mix: out[o,m,n] = bias[o] + sum_t theta[t,o] * plane_t[m,n]
__global__ void __launch_bounds__(256)
k_mix(const float* __restrict__ x, const float* __restrict__ theta,
      const float* __restrict__ bias, float* __restrict__ out)
{
    __shared__ float sh_th[25 * OUTC];
    __shared__ float sh_b[OUTC];
    const int tid = threadIdx.x;
    for (int t = tid; t < 25 * OUTC; t += 256) sh_th[t] = theta[t];
    if (tid < OUTC) sh_b[tid] = bias[tid];
    __syncthreads();

    const int off = (blockIdx.x * 256 + tid) * 2;

    float2 v[25];
    v[0] = *(const float2*)(x + off);
#pragma unroll
    for (int j = 1; j <= 4; ++j) v[j] = *(const float2*)(g_W32[j - 1] + off);
#pragma unroll
    for (int i = 1; i <= 4; ++i) v[i * 5] = *(const float2*)(g_Y32[i - 1] + off);
#pragma unroll
    for (int i = 1; i <= 4; ++i)
#pragma unroll
        for (int j = 1; j <= 4; ++j)
            v[i * 5 + j] = *(const float2*)(g_Z32[(i - 1) * 4 + (j - 1)] + off);

#pragma unroll
    for (int o = 0; o < OUTC; ++o) {
        float sx = sh_b[o], sy = sh_b[o];
#pragma unroll
        for (int t = 0; t < 25; ++t) {
            const float w = sh_th[t * OUTC + o];
            sx += w * v[t].x;
            sy += w * v[t].y;
        }
        *(float2*)(out + (size_t)o * N2 + off) = make_float2(sx, sy);
    }
}

// ----------------------------------------------------------------------------
extern "C" void kernel_launch(void* const* d_in, const int* in_sizes, int n_in,
                              void* d_out, int out_size)
{
    const float* x     = (const float*)d_in[0];
    const float* Lr    = (const float*)d_in[1];
    const float* Lc    = (const float*)d_in[2];
    const float* theta = (const float*)d_in[3];
    const float* bias  = (const float*)d_in[4];
    float* out = (float*)d_out;

    cudaFuncSetAttribute(k_y, cudaFuncAttributeMaxDynamicSharedMemorySize, SMEM_DYN1);
    cudaFuncSetAttribute(k_w, cudaFuncAttributeMaxDynamicSharedMemorySize, SMEM_DYN1);
    cudaFuncSetAttribute(k_z, cudaFuncAttributeMaxDynamicSharedMemorySize, SMEM_DYN1);

    const dim3 blk(512);
    const dim3 g2(NM / 128, NM / 128, 1);        // (12,12)
    const dim3 blkT(32, 8);
    const dim3 gT(NM / 32, NM / 32, 1);

    // input conversions
    k_cvt<<<dim3(N2 / 1024, 1, 3), 256>>>(x, Lr, Lc);
    k_cvtT<<<gT, blkT>>>(x);

    // Y chain (sequential; interleave W steps to fill gaps around transposes)
    k_y<<<g2, blk, SMEM_DYN1>>>(x, 0);
    k_w<<<g2, blk, SMEM_DYN1>>>(x, 0);
    k_trY<<<gT, blkT>>>(0);
    k_y<<<g2, blk, SMEM_DYN1>>>(x, 1);
    k_w<<<g2, blk, SMEM_DYN1>>>(x, 1);
    k_trY<<<gT, blkT>>>(1);
    k_y<<<g2, blk, SMEM_DYN1>>>(x, 2);
    k_w<<<g2, blk, SMEM_DYN1>>>(x, 2);
    k_trY<<<gT, blkT>>>(2);
    k_y<<<g2, blk, SMEM_DYN1>>>(x, 3);
    k_w<<<g2, blk, SMEM_DYN1>>>(x, 3);

    // Z chains (4 steps, each batched over i)
    for (int s = 0; s < 4; ++s)
        k_z<<<dim3(12, 12, 4), blk, SMEM_DYN1>>>(s);

    // final 25-term mix
    k_mix<<<N2 / 512, 256>>>(x, theta, bias, out);
}

// round 14
// speedup vs baseline: 1.4237x; 1.4237x over previous
#include <cuda_runtime.h>
#include <cuda_fp16.h>
#include <cstdint>

// ============================================================================
// BilinearChebConv via mma.sync, T2-composition recursion, fully batched.
// out[o] = sum_{i,j} theta[i,j,o] * (Tr_i @ X @ Tc_j) + bias[o]
// M = N = 1536, orders 4/4, OUT = 32.
// R14: 26 MMA units in 5 batched GEMM launches (grid >= 576 each):
//   T2 = 2L@L - I per side; then T_{k+2} = 2 T2 T_k - T_{k-2}, T3 = 2 T2 T1 - T1
//   applied directly to the planes. Sequential depth 9 launches total.
// All GEMMs 1-term fp16-hi x fp16-hi, fp32 accumulate, exact fp32 D.
// ============================================================================

constexpr int NM   = 1536;
constexpr int N2   = NM * NM;
constexpr int OUTC = 32;

constexpr int BK     = 64;
constexpr int NKT    = NM / BK;             // 24
constexpr int PLANE  = 128 * 128;
constexpr int STAGE1 = 2 * PLANE;           // 32 KB
constexpr unsigned SMEM_DYN1 = 3 * STAGE1;  // 96 KB

// ----------------------------------------------------------------------------
// Scratch
__device__ float g_Y32[4][N2];
__device__ float g_W32[4][N2];
__device__ float g_Z32[16][N2];         // idx (i-1)*4 + (j-1)
// fp16 planes
__device__ __half g_Xh[N2], g_XTh[N2];
__device__ __half g_Lrh[N2], g_Lch[N2];
__device__ __half g_T2rh[N2], g_T2ch[N2];     // symmetric
__device__ __half g_Yh[4][N2];                // Y_i row-major (A for Z)
__device__ __half g_YTh[2][N2];               // Y1^T, Y2^T
__device__ __half g_Wh[2][N2];                // W1, W2 (A for W3, W4)
__device__ __half g_Z1h[4][N2], g_Z2h[4][N2]; // Z_{i,1}, Z_{i,2} (A for Z3/Z4)

// ----------------------------------------------------------------------------
__device__ __forceinline__ uint32_t smem_u32(const void* p) {
    uint32_t a;
    asm("{ .reg .u64 t; cvta.to.shared.u64 t, %1; cvt.u32.u64 %0, t; }"
        : "=r"(a) : "l"(p));
    return a;
}
__device__ __forceinline__ void cpa16(uint32_t s, const void* g) {
    asm volatile("cp.async.cg.shared.global [%0], [%1], 16;\n" :: "r"(s), "l"(g));
}
__device__ __forceinline__ void cp_commit() {
    asm volatile("cp.async.commit_group;\n" ::: "memory");
}
__device__ __forceinline__ void cp_wait2() {
    asm volatile("cp.async.wait_group 2;\n" ::: "memory");
}
__device__ __forceinline__ void ldsm4(uint32_t* r, uint32_t a) {
    asm volatile("ldmatrix.sync.aligned.m8n8.x4.shared.b16 {%0,%1,%2,%3}, [%4];"
                 : "=r"(r[0]), "=r"(r[1]), "=r"(r[2]), "=r"(r[3]) : "r"(a));
}
__device__ __forceinline__ void mma16816(float* c, const uint32_t* a,
                                         uint32_t b0, uint32_t b1) {
    asm volatile("mma.sync.aligned.m16n8k16.row.col.f32.f16.f16.f32 "
                 "{%0,%1,%2,%3}, {%4,%5,%6,%7}, {%8,%9}, {%0,%1,%2,%3};"
                 : "+f"(c[0]), "+f"(c[1]), "+f"(c[2]), "+f"(c[3])
                 : "r"(a[0]), "r"(a[1]), "r"(a[2]), "r"(a[3]), "r"(b0), "r"(b1));
}

extern __shared__ char dsm[];

// ----------------------------------------------------------------------------
// 1-term core GEMM: C(128x128) += Ah * Bh(NxK) over K=1536.
// ----------------------------------------------------------------------------
__device__ __forceinline__ void gemm_main1(
    const __half* __restrict__ Ah, const __half* __restrict__ Bh,
    float (&acc)[2][4][4])
{
    const uint32_t sbase = smem_u32(dsm);
    const int tid = threadIdx.x, lane = tid & 31, wid = tid >> 5;
    const int wm = (wid & 3) * 32, wn = (wid >> 2) * 32;
    const int l15 = lane & 15, lhi = lane >> 4;
    const int bm = blockIdx.y * 128, bn = blockIdx.x * 128;
    const int lc = tid & 7, lr = tid >> 3;

    auto load_stage = [&](int st, int kc) {
        const uint32_t sb = sbase + st * STAGE1;
#pragma unroll
        for (int rr = 0; rr < 128; rr += 64) {
            const int r = lr + rr;
            const uint32_t off = (uint32_t)(r * 128) + (uint32_t)((lc ^ (r & 7)) << 4);
            const size_t ga = (size_t)(bm + r) * NM + kc + lc * 8;
            const size_t gb = (size_t)(bn + r) * NM + kc + lc * 8;
            cpa16(sb + 0 * PLANE + off, Ah + ga);
            cpa16(sb + 1 * PLANE + off, Bh + gb);
        }
    };

    load_stage(0, 0);      cp_commit();
    load_stage(1, BK);     cp_commit();
    load_stage(2, 2 * BK); cp_commit();

    for (int kt = 0; kt < NKT; ++kt) {
        cp_wait2();
        __syncthreads();
        const uint32_t sb = sbase + (kt % 3) * STAGE1;
#pragma unroll
        for (int kh = 0; kh < 4; ++kh) {
            uint32_t ahf[2][4];
            const int chunkL = (kh << 1) | lhi;
#pragma unroll
            for (int mt = 0; mt < 2; ++mt) {
                const int r = wm + mt * 16 + l15;
                const uint32_t off = (uint32_t)(r * 128) +
                                     (uint32_t)((chunkL ^ (r & 7)) << 4);
                ldsm4(ahf[mt], sb + 0 * PLANE + off);
            }
#pragma unroll
            for (int g = 0; g < 2; ++g) {
                uint32_t bh4[4];
                const int r = wn + g * 16 + l15;
                const uint32_t off = (uint32_t)(r * 128) +
                                     (uint32_t)((chunkL ^ (r & 7)) << 4);
                ldsm4(bh4, sb + 1 * PLANE + off);
#pragma unroll
                for (int mt = 0; mt < 2; ++mt)
#pragma unroll
                    for (int j = 0; j < 2; ++j)
                        mma16816(acc[mt][g * 2 + j], ahf[mt], bh4[j], bh4[j + 2]);
            }
        }
        __syncthreads();
        if (kt + 3 < NKT) load_stage(kt % 3, (kt + 3) * BK);
        cp_commit();
    }
}

// ----------------------------------------------------------------------------
// Job descriptor: dmode 0: C=acc; 1: C=2acc-D; 2: C=2acc-I. C/H nullable.
struct Job {
    const __half* A;
    const __half* B;
    const float*  D;
    float*        C;
    __half*       H;
    int           dmode;
};

__device__ __forceinline__ Job get_job(int lid, int z, const float* x)
{
    Job j{nullptr, nullptr, nullptr, nullptr, nullptr, 0};
    if (lid == 1) {
        switch (z) {
        case 0: j = {g_Lrh, g_Lrh, nullptr, nullptr,   g_T2rh,  2}; break; // T2r
        case 1: j = {g_Lch, g_Lch, nullptr, nullptr,   g_T2ch,  2}; break; // T2c
        case 2: j = {g_Lrh, g_XTh, nullptr, g_Y32[0],  g_Yh[0], 0}; break; // Y1
        case 3: j = {g_Xh,  g_Lch, nullptr, g_W32[0],  g_Wh[0], 0}; break; // W1
        }
    } else if (lid == 2) {
        switch (z) {
        case 0: j = {g_T2rh, g_XTh,    nullptr,  g_Y32[1], g_Yh[1], 0}; break; // Y2
        case 1: j = {g_Xh,   g_T2ch,   nullptr,  g_W32[1], g_Wh[1], 0}; break; // W2
        case 2: j = {g_T2rh, g_YTh[0], g_Y32[0], g_Y32[2], g_Yh[2], 1}; break; // Y3
        case 3: j = {g_Wh[0], g_T2ch,  g_W32[0], g_W32[2], nullptr, 1}; break; // W3
        }
    } else if (lid == 3) {
        switch (z) {
        case 0: j = {g_T2rh, g_YTh[1], x, g_Y32[3], g_Yh[3], 1}; break;        // Y4
        case 1: j = {g_Wh[1], g_T2ch,  x, g_W32[3], nullptr, 1}; break;        // W4
        case 2: j = {g_Yh[0], g_Lch,  nullptr, g_Z32[0], g_Z1h[0], 0}; break;  // Z11
        case 3: j = {g_Yh[0], g_T2ch, nullptr, g_Z32[1], g_Z2h[0], 0}; break;  // Z12
        case 4: j = {g_Yh[1], g_Lch,  nullptr, g_Z32[4], g_Z1h[1], 0}; break;  // Z21
        case 5: j = {g_Yh[1], g_T2ch, nullptr, g_Z32[5], g_Z2h[1], 0}; break;  // Z22
        }
    } else if (lid == 4) {
        switch (z) {
        case 0: j = {g_Yh[2], g_Lch,  nullptr, g_Z32[8],  g_Z1h[2], 0}; break; // Z31
        case 1: j = {g_Yh[2], g_T2ch, nullptr, g_Z32[9],  g_Z2h[2], 0}; break; // Z32
        case 2: j = {g_Yh[3], g_Lch,  nullptr, g_Z32[12], g_Z1h[3], 0}; break; // Z41
        case 3: j = {g_Yh[3], g_T2ch, nullptr, g_Z32[13], g_Z2h[3], 0}; break; // Z42
        case 4: j = {g_Z1h[0], g_T2ch, g_Z32[0], g_Z32[2], nullptr, 1}; break; // Z13
        case 5: j = {g_Z2h[0], g_T2ch, g_Y32[0], g_Z32[3], nullptr, 1}; break; // Z14
        case 6: j = {g_Z1h[1], g_T2ch, g_Z32[4], g_Z32[6], nullptr, 1}; break; // Z23
        case 7: j = {g_Z2h[1], g_T2ch, g_Y32[1], g_Z32[7], nullptr, 1}; break; // Z24
        }
    } else { // lid == 5
        switch (z) {
        case 0: j = {g_Z1h[2], g_T2ch, g_Z32[8],  g_Z32[10], nullptr, 1}; break; // Z33
        case 1: j = {g_Z2h[2], g_T2ch, g_Y32[2],  g_Z32[11], nullptr, 1}; break; // Z34
        case 2: j = {g_Z1h[3], g_T2ch, g_Z32[12], g_Z32[14], nullptr, 1}; break; // Z43
        case 3: j = {g_Z2h[3], g_T2ch, g_Y32[3],  g_Z32[15], nullptr, 1}; break; // Z44
        }
    }
    return j;
}

// generic batched GEMM kernel
__global__ void __launch_bounds__(512)
k_batch(int lid, const float* __restrict__ x)
{
    const Job jb = get_job(lid, blockIdx.z, x);
    float acc[2][4][4] = {};
    gemm_main1(jb.A, jb.B, acc);

    const int tid = threadIdx.x, lane = tid & 31, wid = tid >> 5;
    const int wm = (wid & 3) * 32, wn = (wid >> 2) * 32;
    const int bm = blockIdx.y * 128, bn = blockIdx.x * 128;
    const int l4 = lane >> 2, l2 = (lane & 3) * 2;
#pragma unroll
    for (int mt = 0; mt < 2; ++mt)
#pragma unroll
        for (int h = 0; h < 2; ++h) {
            const int row = bm + wm + mt * 16 + l4 + h * 8;
#pragma unroll
            for (int nt = 0; nt < 4; ++nt) {
                const int col = bn + wn + nt * 8 + l2;
                const size_t off = (size_t)row * NM + col;
                float vx = acc[mt][nt][2 * h];
                float vy = acc[mt][nt][2 * h + 1];
                if (jb.dmode == 1) {
                    float2 d = *(const float2*)(jb.D + off);
                    vx = 2.f * vx - d.x;
                    vy = 2.f * vy - d.y;
                } else if (jb.dmode == 2) {
                    vx = 2.f * vx - (row == col ? 1.f : 0.f);
                    vy = 2.f * vy - (row == col + 1 ? 1.f : 0.f);
                }
                if (jb.C) *(float2*)(jb.C + off) = make_float2(vx, vy);
                if (jb.H) {
                    __half2 q;
                    q.x = __float2half_rn(vx);
                    q.y = __float2half_rn(vy);
                    *(__half2*)(jb.H + off) = q;
                }
            }
        }
}

// ----------------------------------------------------------------------------
// fp32 -> fp16 conversions
__global__ void __launch_bounds__(256)
k_cvt(const float* __restrict__ x, const float* __restrict__ Lr,
      const float* __restrict__ Lc)
{
    const int zz = blockIdx.z;
    const float* s = (zz == 0) ? x : (zz == 1) ? Lr : Lc;
    __half* H = (zz == 0) ? g_Xh : (zz == 1) ? g_Lrh : g_Lch;
    const int i = (blockIdx.x * 256 + threadIdx.x) * 4;
    float4 v = *(const float4*)(s + i);
    __half2 p;
    p.x = __float2half_rn(v.x); p.y = __float2half_rn(v.y);
    *(__half2*)(H + i) = p;
    p.x = __float2half_rn(v.z); p.y = __float2half_rn(v.w);
    *(__half2*)(H + i + 2) = p;
}

// transpose fp32 source -> fp16 dest (z selects: 0 = X->XTh, 1 = Y1, 2 = Y2)
__global__ void __launch_bounds__(256)
k_tr(const float* __restrict__ X, int which)
{
    const float* S = (which == 0) ? X : g_Y32[which - 1];
    __half* TH = (which == 0) ? g_XTh : g_YTh[which - 1];
    __shared__ float t[32][33];
    const int tx = threadIdx.x, ty = threadIdx.y;
    const int n0 = blockIdx.x * 32, m0 = blockIdx.y * 32;
#pragma unroll
    for (int i = 0; i < 4; ++i)
        t[ty + 8 * i][tx] = S[(size_t)(m0 + ty + 8 * i) * NM + n0 + tx];
    __syncthreads();
#pragma unroll
    for (int i = 0; i < 4; ++i) {
        const int nl = ty + 8 * i;
        TH[(size_t)(n0 + nl) * NM + m0 + tx] = __float2half_rn(t[tx][nl]);
    }
}

// ----------------------------------------------------------------------------
// Final mix
__global__ void __launch_bounds__(256)
k_mix(const float* __restrict__ x, const float* __restrict__ theta,
      const float* __restrict__ bias, float* __restrict__ out)
{
    __shared__ float sh_th[25 * OUTC];
    __shared__ float sh_b[OUTC];
    const int tid = threadIdx.x;
    for (int t = tid; t < 25 * OUTC; t += 256) sh_th[t] = theta[t];
    if (tid < OUTC) sh_b[tid] = bias[tid];
    __syncthreads();

    const int off = (blockIdx.x * 256 + tid) * 2;

    float2 v[25];
    v[0] = *(const float2*)(x + off);
#pragma unroll
    for (int j = 1; j <= 4; ++j) v[j] = *(const float2*)(g_W32[j - 1] + off);
#pragma unroll
    for (int i = 1; i <= 4; ++i) v[i * 5] = *(const float2*)(g_Y32[i - 1] + off);
#pragma unroll
    for (int i = 1; i <= 4; ++i)
#pragma unroll
        for (int j = 1; j <= 4; ++j)
            v[i * 5 + j] = *(const float2*)(g_Z32[(i - 1) * 4 + (j - 1)] + off);

#pragma unroll
    for (int o = 0; o < OUTC; ++o) {
        float sx = sh_b[o], sy = sh_b[o];
#pragma unroll
        for (int t = 0; t < 25; ++t) {
            const float w = sh_th[t * OUTC + o];
            sx += w * v[t].x;
            sy += w * v[t].y;
        }
        *(float2*)(out + (size_t)o * N2 + off) = make_float2(sx, sy);
    }
}

// ----------------------------------------------------------------------------
extern "C" void kernel_launch(void* const* d_in, const int* in_sizes, int n_in,
                              void* d_out, int out_size)
{
    const float* x     = (const float*)d_in[0];
    const float* Lr    = (const float*)d_in[1];
    const float* Lc    = (const float*)d_in[2];
    const float* theta = (const float*)d_in[3];
    const float* bias  = (const float*)d_in[4];
    float* out = (float*)d_out;

    cudaFuncSetAttribute(k_batch, cudaFuncAttributeMaxDynamicSharedMemorySize, SMEM_DYN1);

    const dim3 blk(512);
    const dim3 blkT(32, 8);
    const dim3 gT(NM / 32, NM / 32, 1);

    // conversions
    k_cvt<<<dim3(N2 / 1024, 1, 3), 256>>>(x, Lr, Lc);
    k_tr<<<gT, blkT>>>(x, 0);                              // X^T

    // L1: T2r, T2c, Y1, W1
    k_batch<<<dim3(12, 12, 4), blk, SMEM_DYN1>>>(1, x);
    k_tr<<<gT, blkT>>>(x, 1);                              // Y1^T
    // L2: Y2, W2, Y3, W3
    k_batch<<<dim3(12, 12, 4), blk, SMEM_DYN1>>>(2, x);
    k_tr<<<gT, blkT>>>(x, 2);                              // Y2^T
    // L3: Y4, W4, Z11, Z12, Z21, Z22
    k_batch<<<dim3(12, 12, 6), blk, SMEM_DYN1>>>(3, x);
    // L4: Z31, Z32, Z41, Z42, Z13, Z14, Z23, Z24
    k_batch<<<dim3(12, 12, 8), blk, SMEM_DYN1>>>(4, x);
    // L5: Z33, Z34, Z43, Z44
    k_batch<<<dim3(12, 12, 4), blk, SMEM_DYN1>>>(5, x);

    // final mix
    k_mix<<<N2 / 512, 256>>>(x, theta, bias, out);
}

// round 15
// speedup vs baseline: 1.5010x; 1.0543x over previous
#include <cuda_runtime.h>
#include <cuda_fp16.h>
#include <cstdint>

// ============================================================================
// BilinearChebConv via mma.sync, T2-composition recursion, fully batched.
// R15 = R14 dataflow (26 one-term GEMM units, 5 batched launches) with fat
// warp tiles: CTA 128x256, 256 threads, 8 warps of 64x64. ldsm:MMA cycle
// ratio drops 1024:1024 -> 512:2048 per 2-tile stage => tensor ~80% predicted.
// ============================================================================

constexpr int NM   = 1536;
constexpr int N2   = NM * NM;
constexpr int OUTC = 32;

constexpr int BK      = 64;
constexpr int NKT     = NM / BK;            // 24
constexpr int APLANE  = 128 * 128;          // 16 KB (A: 128 rows x 128B)
constexpr int BPLANE  = 256 * 128;          // 32 KB (B: 256 rows x 128B)
constexpr int STAGE   = APLANE + BPLANE;    // 48 KB
constexpr unsigned SMEM_DYN = 3 * STAGE;    // 144 KB

// ----------------------------------------------------------------------------
// Scratch
__device__ float g_Y32[4][N2];
__device__ float g_W32[4][N2];
__device__ float g_Z32[16][N2];         // idx (i-1)*4 + (j-1)
// fp16 planes
__device__ __half g_Xh[N2], g_XTh[N2];
__device__ __half g_Lrh[N2], g_Lch[N2];
__device__ __half g_T2rh[N2], g_T2ch[N2];     // symmetric
__device__ __half g_Yh[4][N2];                // Y_i row-major (A for Z)
__device__ __half g_YTh[2][N2];               // Y1^T, Y2^T
__device__ __half g_Wh[2][N2];                // W1, W2 (A for W3, W4)
__device__ __half g_Z1h[4][N2], g_Z2h[4][N2]; // Z_{i,1}, Z_{i,2} (A for Z3/Z4)

// ----------------------------------------------------------------------------
__device__ __forceinline__ uint32_t smem_u32(const void* p) {
    uint32_t a;
    asm("{ .reg .u64 t; cvta.to.shared.u64 t, %1; cvt.u32.u64 %0, t; }"
        : "=r"(a) : "l"(p));
    return a;
}
__device__ __forceinline__ void cpa16(uint32_t s, const void* g) {
    asm volatile("cp.async.cg.shared.global [%0], [%1], 16;\n" :: "r"(s), "l"(g));
}
__device__ __forceinline__ void cp_commit() {
    asm volatile("cp.async.commit_group;\n" ::: "memory");
}
__device__ __forceinline__ void cp_wait2() {
    asm volatile("cp.async.wait_group 2;\n" ::: "memory");
}
__device__ __forceinline__ void ldsm4(uint32_t* r, uint32_t a) {
    asm volatile("ldmatrix.sync.aligned.m8n8.x4.shared.b16 {%0,%1,%2,%3}, [%4];"
                 : "=r"(r[0]), "=r"(r[1]), "=r"(r[2]), "=r"(r[3]) : "r"(a));
}
__device__ __forceinline__ void mma16816(float* c, const uint32_t* a,
                                         uint32_t b0, uint32_t b1) {
    asm volatile("mma.sync.aligned.m16n8k16.row.col.f32.f16.f16.f32 "
                 "{%0,%1,%2,%3}, {%4,%5,%6,%7}, {%8,%9}, {%0,%1,%2,%3};"
                 : "+f"(c[0]), "+f"(c[1]), "+f"(c[2]), "+f"(c[3])
                 : "r"(a[0]), "r"(a[1]), "r"(a[2]), "r"(a[3]), "r"(b0), "r"(b1));
}

extern __shared__ char dsm[];

// ----------------------------------------------------------------------------
// 1-term core GEMM: C(128x256) += Ah(128xK) * Bh(256-rows x K) over K=1536.
// 256 threads, 8 warps of 64x64. acc[4][8][4] per thread (128 regs).
// ----------------------------------------------------------------------------
__device__ __forceinline__ void gemm_main1(
    const __half* __restrict__ Ah, const __half* __restrict__ Bh,
    float (&acc)[4][8][4])
{
    const uint32_t sbase = smem_u32(dsm);
    const int tid = threadIdx.x, lane = tid & 31, wid = tid >> 5;
    const int wm = (wid & 1) * 64, wn = (wid >> 1) * 64;
    const int l15 = lane & 15, lhi = lane >> 4;
    const int bm = blockIdx.y * 128, bn = blockIdx.x * 256;
    const int lc = tid & 7, lr = tid >> 3;        // chunk 0..7, row 0..31

    auto load_stage = [&](int st, int kc) {
        const uint32_t sb = sbase + st * STAGE;
#pragma unroll
        for (int rr = 0; rr < 128; rr += 32) {    // A: 128 rows
            const int r = lr + rr;
            const uint32_t off = (uint32_t)(r * 128) + (uint32_t)((lc ^ (r & 7)) << 4);
            cpa16(sb + off, Ah + (size_t)(bm + r) * NM + kc + lc * 8);
        }
#pragma unroll
        for (int rr = 0; rr < 256; rr += 32) {    // B: 256 rows
            const int r = lr + rr;
            const uint32_t off = (uint32_t)(r * 128) + (uint32_t)((lc ^ (r & 7)) << 4);
            cpa16(sb + APLANE + off, Bh + (size_t)(bn + r) * NM + kc + lc * 8);
        }
    };

    load_stage(0, 0);      cp_commit();
    load_stage(1, BK);     cp_commit();
    load_stage(2, 2 * BK); cp_commit();

    for (int kt = 0; kt < NKT; ++kt) {
        cp_wait2();
        __syncthreads();
        const uint32_t sb = sbase + (kt % 3) * STAGE;
#pragma unroll
        for (int kh = 0; kh < 4; ++kh) {
            uint32_t ahf[4][4];
            const int chunkL = (kh << 1) | lhi;
#pragma unroll
            for (int mt = 0; mt < 4; ++mt) {
                const int r = wm + mt * 16 + l15;
                const uint32_t off = (uint32_t)(r * 128) +
                                     (uint32_t)((chunkL ^ (r & 7)) << 4);
                ldsm4(ahf[mt], sb + off);
            }
#pragma unroll
            for (int g = 0; g < 4; ++g) {
                uint32_t bh4[4];
                const int r = wn + g * 16 + l15;
                const uint32_t off = (uint32_t)(r * 128) +
                                     (uint32_t)((chunkL ^ (r & 7)) << 4);
                ldsm4(bh4, sb + APLANE + off);
#pragma unroll
                for (int mt = 0; mt < 4; ++mt)
#pragma unroll
                    for (int j = 0; j < 2; ++j)
                        mma16816(acc[mt][g * 2 + j], ahf[mt], bh4[j], bh4[j + 2]);
            }
        }
        __syncthreads();
        if (kt + 3 < NKT) load_stage(kt % 3, (kt + 3) * BK);
        cp_commit();
    }
}

// ----------------------------------------------------------------------------
// Job descriptor: dmode 0: C=acc; 1: C=2acc-D; 2: C=2acc-I. C/H nullable.
struct Job {
    const __half* A;
    const __half* B;
    const float*  D;
    float*        C;
    __half*       H;
    int           dmode;
};

__device__ __forceinline__ Job get_job(int lid, int z, const float* x)
{
    Job j{nullptr, nullptr, nullptr, nullptr, nullptr, 0};
    if (lid == 1) {
        switch (z) {
        case 0: j = {g_Lrh, g_Lrh, nullptr, nullptr,   g_T2rh,  2}; break; // T2r
        case 1: j = {g_Lch, g_Lch, nullptr, nullptr,   g_T2ch,  2}; break; // T2c
        case 2: j = {g_Lrh, g_XTh, nullptr, g_Y32[0],  g_Yh[0], 0}; break; // Y1
        case 3: j = {g_Xh,  g_Lch, nullptr, g_W32[0],  g_Wh[0], 0}; break; // W1
        }
    } else if (lid == 2) {
        switch (z) {
        case 0: j = {g_T2rh, g_XTh,    nullptr,  g_Y32[1], g_Yh[1], 0}; break; // Y2
        case 1: j = {g_Xh,   g_T2ch,   nullptr,  g_W32[1], g_Wh[1], 0}; break; // W2
        case 2: j = {g_T2rh, g_YTh[0], g_Y32[0], g_Y32[2], g_Yh[2], 1}; break; // Y3
        case 3: j = {g_Wh[0], g_T2ch,  g_W32[0], g_W32[2], nullptr, 1}; break; // W3
        }
    } else if (lid == 3) {
        switch (z) {
        case 0: j = {g_T2rh, g_YTh[1], x, g_Y32[3], g_Yh[3], 1}; break;        // Y4
        case 1: j = {g_Wh[1], g_T2ch,  x, g_W32[3], nullptr, 1}; break;        // W4
        case 2: j = {g_Yh[0], g_Lch,  nullptr, g_Z32[0], g_Z1h[0], 0}; break;  // Z11
        case 3: j = {g_Yh[0], g_T2ch, nullptr, g_Z32[1], g_Z2h[0], 0}; break;  // Z12
        case 4: j = {g_Yh[1], g_Lch,  nullptr, g_Z32[4], g_Z1h[1], 0}; break;  // Z21
        case 5: j = {g_Yh[1], g_T2ch, nullptr, g_Z32[5], g_Z2h[1], 0}; break;  // Z22
        }
    } else if (lid == 4) {
        switch (z) {
        case 0: j = {g_Yh[2], g_Lch,  nullptr, g_Z32[8],  g_Z1h[2], 0}; break; // Z31
        case 1: j = {g_Yh[2], g_T2ch, nullptr, g_Z32[9],  g_Z2h[2], 0}; break; // Z32
        case 2: j = {g_Yh[3], g_Lch,  nullptr, g_Z32[12], g_Z1h[3], 0}; break; // Z41
        case 3: j = {g_Yh[3], g_T2ch, nullptr, g_Z32[13], g_Z2h[3], 0}; break; // Z42
        case 4: j = {g_Z1h[0], g_T2ch, g_Z32[0], g_Z32[2], nullptr, 1}; break; // Z13
        case 5: j = {g_Z2h[0], g_T2ch, g_Y32[0], g_Z32[3], nullptr, 1}; break; // Z14
        case 6: j = {g_Z1h[1], g_T2ch, g_Z32[4], g_Z32[6], nullptr, 1}; break; // Z23
        case 7: j = {g_Z2h[1], g_T2ch, g_Y32[1], g_Z32[7], nullptr, 1}; break; // Z24
        }
    } else { // lid == 5
        switch (z) {
        case 0: j = {g_Z1h[2], g_T2ch, g_Z32[8],  g_Z32[10], nullptr, 1}; break; // Z33
        case 1: j = {g_Z2h[2], g_T2ch, g_Y32[2],  g_Z32[11], nullptr, 1}; break; // Z34
        case 2: j = {g_Z1h[3], g_T2ch, g_Z32[12], g_Z32[14], nullptr, 1}; break; // Z43
        case 3: j = {g_Z2h[3], g_T2ch, g_Y32[3],  g_Z32[15], nullptr, 1}; break; // Z44
        }
    }
    return j;
}

// generic batched GEMM kernel (CTA 128x256)
__global__ void __launch_bounds__(256, 1)
k_batch(int lid, const float* __restrict__ x)
{
    const Job jb = get_job(lid, blockIdx.z, x);
    float acc[4][8][4] = {};
    gemm_main1(jb.A, jb.B, acc);

    const int tid = threadIdx.x, lane = tid & 31, wid = tid >> 5;
    const int wm = (wid & 1) * 64, wn = (wid >> 1) * 64;
    const int bm = blockIdx.y * 128, bn = blockIdx.x * 256;
    const int l4 = lane >> 2, l2 = (lane & 3) * 2;
#pragma unroll
    for (int mt = 0; mt < 4; ++mt)
#pragma unroll
        for (int h = 0; h < 2; ++h) {
            const int row = bm + wm + mt * 16 + l4 + h * 8;
#pragma unroll
            for (int nt = 0; nt < 8; ++nt) {
                const int col = bn + wn + nt * 8 + l2;
                const size_t off = (size_t)row * NM + col;
                float vx = acc[mt][nt][2 * h];
                float vy = acc[mt][nt][2 * h + 1];
                if (jb.dmode == 1) {
                    float2 d = *(const float2*)(jb.D + off);
                    vx = 2.f * vx - d.x;
                    vy = 2.f * vy - d.y;
                } else if (jb.dmode == 2) {
                    vx = 2.f * vx - (row == col ? 1.f : 0.f);
                    vy = 2.f * vy - (row == col + 1 ? 1.f : 0.f);
                }
                if (jb.C) *(float2*)(jb.C + off) = make_float2(vx, vy);
                if (jb.H) {
                    __half2 q;
                    q.x = __float2half_rn(vx);
                    q.y = __float2half_rn(vy);
                    *(__half2*)(jb.H + off) = q;
                }
            }
        }
}

// ----------------------------------------------------------------------------
// fp32 -> fp16 conversions
__global__ void __launch_bounds__(256)
k_cvt(const float* __restrict__ x, const float* __restrict__ Lr,
      const float* __restrict__ Lc)
{
    const int zz = blockIdx.z;
    const float* s = (zz == 0) ? x : (zz == 1) ? Lr : Lc;
    __half* H = (zz == 0) ? g_Xh : (zz == 1) ? g_Lrh : g_Lch;
    const int i = (blockIdx.x * 256 + threadIdx.x) * 4;
    float4 v = *(const float4*)(s + i);
    __half2 p;
    p.x = __float2half_rn(v.x); p.y = __float2half_rn(v.y);
    *(__half2*)(H + i) = p;
    p.x = __float2half_rn(v.z); p.y = __float2half_rn(v.w);
    *(__half2*)(H + i + 2) = p;
}

// transpose fp32 source -> fp16 dest (which: 0 = X->XTh, 1 = Y1, 2 = Y2)
__global__ void __launch_bounds__(256)
k_tr(const float* __restrict__ X, int which)
{
    const float* S = (which == 0) ? X : g_Y32[which - 1];
    __half* TH = (which == 0) ? g_XTh : g_YTh[which - 1];
    __shared__ float t[32][33];
    const int tx = threadIdx.x, ty = threadIdx.y;
    const int n0 = blockIdx.x * 32, m0 = blockIdx.y * 32;
#pragma unroll
    for (int i = 0; i < 4; ++i)
        t[ty + 8 * i][tx] = S[(size_t)(m0 + ty + 8 * i) * NM + n0 + tx];
    __syncthreads();
#pragma unroll
    for (int i = 0; i < 4; ++i) {
        const int nl = ty + 8 * i;
        TH[(size_t)(n0 + nl) * NM + m0 + tx] = __float2half_rn(t[tx][nl]);
    }
}

// ----------------------------------------------------------------------------
// Final mix
__global__ void __launch_bounds__(256)
k_mix(const float* __restrict__ x, const float* __restrict__ theta,
      const float* __restrict__ bias, float* __restrict__ out)
{
    __shared__ float sh_th[25 * OUTC];
    __shared__ float sh_b[OUTC];
    const int tid = threadIdx.x;
    for (int t = tid; t < 25 * OUTC; t += 256) sh_th[t] = theta[t];
    if (tid < OUTC) sh_b[tid] = bias[tid];
    __syncthreads();

    const int off = (blockIdx.x * 256 + tid) * 2;

    float2 v[25];
    v[0] = *(const float2*)(x + off);
#pragma unroll
    for (int j = 1; j <= 4; ++j) v[j] = *(const float2*)(g_W32[j - 1] + off);
#pragma unroll
    for (int i = 1; i <= 4; ++i) v[i * 5] = *(const float2*)(g_Y32[i - 1] + off);
#pragma unroll
    for (int i = 1; i <= 4; ++i)
#pragma unroll
        for (int j = 1; j <= 4; ++j)
            v[i * 5 + j] = *(const float2*)(g_Z32[(i - 1) * 4 + (j - 1)] + off);

#pragma unroll
    for (int o = 0; o < OUTC; ++o) {
        float sx = sh_b[o], sy = sh_b[o];
#pragma unroll
        for (int t = 0; t < 25; ++t) {
            const float w = sh_th[t * OUTC + o];
            sx += w * v[t].x;
            sy += w * v[t].y;
        }
        *(float2*)(out + (size_t)o * N2 + off) = make_float2(sx, sy);
    }
}

// ----------------------------------------------------------------------------
extern "C" void kernel_launch(void* const* d_in, const int* in_sizes, int n_in,
                              void* d_out, int out_size)
{
    const float* x     = (const float*)d_in[0];
    const float* Lr    = (const float*)d_in[1];
    const float* Lc    = (const float*)d_in[2];
    const float* theta = (const float*)d_in[3];
    const float* bias  = (const float*)d_in[4];
    float* out = (float*)d_out;

    cudaFuncSetAttribute(k_batch, cudaFuncAttributeMaxDynamicSharedMemorySize, SMEM_DYN);

    const dim3 blk(256);
    const dim3 blkT(32, 8);
    const dim3 gT(NM / 32, NM / 32, 1);

    // conversions
    k_cvt<<<dim3(N2 / 1024, 1, 3), 256>>>(x, Lr, Lc);
    k_tr<<<gT, blkT>>>(x, 0);                              // X^T

    // L1: T2r, T2c, Y1, W1
    k_batch<<<dim3(6, 12, 4), blk, SMEM_DYN>>>(1, x);
    k_tr<<<gT, blkT>>>(x, 1);                              // Y1^T
    // L2: Y2, W2, Y3, W3
    k_batch<<<dim3(6, 12, 4), blk, SMEM_DYN>>>(2, x);
    k_tr<<<gT, blkT>>>(x, 2);                              // Y2^T
    // L3: Y4, W4, Z11, Z12, Z21, Z22
    k_batch<<<dim3(6, 12, 6), blk, SMEM_DYN>>>(3, x);
    // L4: Z31, Z32, Z41, Z42, Z13, Z14, Z23, Z24
    k_batch<<<dim3(6, 12, 8), blk, SMEM_DYN>>>(4, x);
    // L5: Z33, Z34, Z43, Z44
    k_batch<<<dim3(6, 12, 4), blk, SMEM_DYN>>>(5, x);

    // final mix
    k_mix<<<N2 / 512, 256>>>(x, theta, bias, out);
}

// round 16
// speedup vs baseline: 1.5275x; 1.0177x over previous
#include <cuda_runtime.h>
#include <cuda_fp16.h>
#include <cstdint>

// ============================================================================
// BilinearChebConv via mma.sync, T2-composition recursion, fully batched.
// R16 = R15 (26 one-term GEMM units, CTA 128x256, 8 warps of 64x64) plus:
//  - 4-stage cp.async pipeline, load-first, one __syncthreads per stage
//  - terminal planes (W3,W4, Z_{i,2..4}) written fp16-only (no dead fp32 C)
//  - k_mix reads all 24 derived planes in fp16 (122 MB vs 236 MB)
// ============================================================================

constexpr int NM   = 1536;
constexpr int N2   = NM * NM;
constexpr int OUTC = 32;

constexpr int BK      = 64;
constexpr int NKT     = NM / BK;            // 24
constexpr int APLANE  = 128 * 128;          // 16 KB
constexpr int BPLANE  = 256 * 128;          // 32 KB
constexpr int STAGE   = APLANE + BPLANE;    // 48 KB
constexpr unsigned SMEM_DYN = 4 * STAGE;    // 192 KB

// ----------------------------------------------------------------------------
// Scratch
__device__ float g_Y32[4][N2];              // fp32 (mix + D operands)
__device__ float g_W32[2][N2];              // W1, W2 fp32 (D operands)
__device__ float g_Z1f[4][N2];              // Z_{i,1} fp32 (D for Z_{i,3})
// fp16 planes
__device__ __half g_Xh[N2], g_XTh[N2];
__device__ __half g_Lrh[N2], g_Lch[N2];
__device__ __half g_T2rh[N2], g_T2ch[N2];       // symmetric
__device__ __half g_Yh[4][N2];                  // Y_i (A for Z, mix)
__device__ __half g_YTh[2][N2];                 // Y1^T, Y2^T
__device__ __half g_Wh[4][N2];                  // W1..W4 (A ops + mix)
__device__ __half g_Z1h[4][N2], g_Z2h[4][N2];   // Z_{i,1}, Z_{i,2}
__device__ __half g_Z3h[4][N2], g_Z4h[4][N2];   // Z_{i,3}, Z_{i,4} (mix only)

// ----------------------------------------------------------------------------
__device__ __forceinline__ uint32_t smem_u32(const void* p) {
    uint32_t a;
    asm("{ .reg .u64 t; cvta.to.shared.u64 t, %1; cvt.u32.u64 %0, t; }"
        : "=r"(a) : "l"(p));
    return a;
}
__device__ __forceinline__ void cpa16(uint32_t s, const void* g) {
    asm volatile("cp.async.cg.shared.global [%0], [%1], 16;\n" :: "r"(s), "l"(g));
}
__device__ __forceinline__ void cp_commit() {
    asm volatile("cp.async.commit_group;\n" ::: "memory");
}
__device__ __forceinline__ void cp_wait2() {
    asm volatile("cp.async.wait_group 2;\n" ::: "memory");
}
__device__ __forceinline__ void ldsm4(uint32_t* r, uint32_t a) {
    asm volatile("ldmatrix.sync.aligned.m8n8.x4.shared.b16 {%0,%1,%2,%3}, [%4];"
                 : "=r"(r[0]), "=r"(r[1]), "=r"(r[2]), "=r"(r[3]) : "r"(a));
}
__device__ __forceinline__ void mma16816(float* c, const uint32_t* a,
                                         uint32_t b0, uint32_t b1) {
    asm volatile("mma.sync.aligned.m16n8k16.row.col.f32.f16.f16.f32 "
                 "{%0,%1,%2,%3}, {%4,%5,%6,%7}, {%8,%9}, {%0,%1,%2,%3};"
                 : "+f"(c[0]), "+f"(c[1]), "+f"(c[2]), "+f"(c[3])
                 : "r"(a[0]), "r"(a[1]), "r"(a[2]), "r"(a[3]), "r"(b0), "r"(b1));
}

extern __shared__ char dsm[];

// ----------------------------------------------------------------------------
// 1-term core GEMM: C(128x256) += Ah(128xK) * Bh(256 rows x K) over K=1536.
// 256 threads, 8 warps of 64x64. acc[4][8][4]. 4-stage pipeline, load-first.
// ----------------------------------------------------------------------------
__device__ __forceinline__ void gemm_main1(
    const __half* __restrict__ Ah, const __half* __restrict__ Bh,
    float (&acc)[4][8][4])
{
    const uint32_t sbase = smem_u32(dsm);
    const int tid = threadIdx.x, lane = tid & 31, wid = tid >> 5;
    const int wm = (wid & 1) * 64, wn = (wid >> 1) * 64;
    const int l15 = lane & 15, lhi = lane >> 4;
    const int bm = blockIdx.y * 128, bn = blockIdx.x * 256;
    const int lc = tid & 7, lr = tid >> 3;        // chunk 0..7, row 0..31

    auto load_stage = [&](int st, int kc) {
        const uint32_t sb = sbase + st * STAGE;
#pragma unroll
        for (int rr = 0; rr < 128; rr += 32) {
            const int r = lr + rr;
            const uint32_t off = (uint32_t)(r * 128) + (uint32_t)((lc ^ (r & 7)) << 4);
            cpa16(sb + off, Ah + (size_t)(bm + r) * NM + kc + lc * 8);
        }
#pragma unroll
        for (int rr = 0; rr < 256; rr += 32) {
            const int r = lr + rr;
            const uint32_t off = (uint32_t)(r * 128) + (uint32_t)((lc ^ (r & 7)) << 4);
            cpa16(sb + APLANE + off, Bh + (size_t)(bn + r) * NM + kc + lc * 8);
        }
    };

    load_stage(0, 0);      cp_commit();
    load_stage(1, BK);     cp_commit();
    load_stage(2, 2 * BK); cp_commit();

    for (int kt = 0; kt < NKT; ++kt) {
        cp_wait2();                 // stage kt resident (<=2 younger pending)
        __syncthreads();            // all warps done computing kt-1
        if (kt + 3 < NKT) load_stage((kt + 3) & 3, (kt + 3) * BK);
        cp_commit();                // constant group accounting
        const uint32_t sb = sbase + (kt & 3) * STAGE;
#pragma unroll
        for (int kh = 0; kh < 4; ++kh) {
            uint32_t ahf[4][4];
            const int chunkL = (kh << 1) | lhi;
#pragma unroll
            for (int mt = 0; mt < 4; ++mt) {
                const int r = wm + mt * 16 + l15;
                const uint32_t off = (uint32_t)(r * 128) +
                                     (uint32_t)((chunkL ^ (r & 7)) << 4);
                ldsm4(ahf[mt], sb + off);
            }
#pragma unroll
            for (int g = 0; g < 4; ++g) {
                uint32_t bh4[4];
                const int r = wn + g * 16 + l15;
                const uint32_t off = (uint32_t)(r * 128) +
                                     (uint32_t)((chunkL ^ (r & 7)) << 4);
                ldsm4(bh4, sb + APLANE + off);
#pragma unroll
                for (int mt = 0; mt < 4; ++mt)
#pragma unroll
                    for (int j = 0; j < 2; ++j)
                        mma16816(acc[mt][g * 2 + j], ahf[mt], bh4[j], bh4[j + 2]);
            }
        }
    }
}

// ----------------------------------------------------------------------------
// Job: dmode 0: V=acc; 1: V=2acc-D; 2: V=2acc-I. C (fp32) / H (fp16) nullable.
struct Job {
    const __half* A;
    const __half* B;
    const float*  D;
    float*        C;
    __half*       H;
    int           dmode;
};

__device__ __forceinline__ Job get_job(int lid, int z, const float* x)
{
    Job j{nullptr, nullptr, nullptr, nullptr, nullptr, 0};
    if (lid == 1) {
        switch (z) {
        case 0: j = {g_Lrh, g_Lrh, nullptr, nullptr,   g_T2rh,  2}; break; // T2r
        case 1: j = {g_Lch, g_Lch, nullptr, nullptr,   g_T2ch,  2}; break; // T2c
        case 2: j = {g_Lrh, g_XTh, nullptr, g_Y32[0],  g_Yh[0], 0}; break; // Y1
        case 3: j = {g_Xh,  g_Lch, nullptr, g_W32[0],  g_Wh[0], 0}; break; // W1
        }
    } else if (lid == 2) {
        switch (z) {
        case 0: j = {g_T2rh, g_XTh,    nullptr,  g_Y32[1], g_Yh[1], 0}; break; // Y2
        case 1: j = {g_Xh,   g_T2ch,   nullptr,  g_W32[1], g_Wh[1], 0}; break; // W2
        case 2: j = {g_T2rh, g_YTh[0], g_Y32[0], g_Y32[2], g_Yh[2], 1}; break; // Y3
        case 3: j = {g_Wh[0], g_T2ch,  g_W32[0], nullptr,  g_Wh[2], 1}; break; // W3
        }
    } else if (lid == 3) {
        switch (z) {
        case 0: j = {g_T2rh, g_YTh[1], x, g_Y32[3], g_Yh[3], 1}; break;        // Y4
        case 1: j = {g_Wh[1], g_T2ch,  x, nullptr,  g_Wh[3], 1}; break;        // W4
        case 2: j = {g_Yh[0], g_Lch,  nullptr, g_Z1f[0], g_Z1h[0], 0}; break;  // Z11
        case 3: j = {g_Yh[0], g_T2ch, nullptr, nullptr,  g_Z2h[0], 0}; break;  // Z12
        case 4: j = {g_Yh[1], g_Lch,  nullptr, g_Z1f[1], g_Z1h[1], 0}; break;  // Z21
        case 5: j = {g_Yh[1], g_T2ch, nullptr, nullptr,  g_Z2h[1], 0}; break;  // Z22
        }
    } else if (lid == 4) {
        switch (z) {
        case 0: j = {g_Yh[2], g_Lch,  nullptr, g_Z1f[2], g_Z1h[2], 0}; break;  // Z31
        case 1: j = {g_Yh[2], g_T2ch, nullptr, nullptr,  g_Z2h[2], 0}; break;  // Z32
        case 2: j = {g_Yh[3], g_Lch,  nullptr, g_Z1f[3], g_Z1h[3], 0}; break;  // Z41
        case 3: j = {g_Yh[3], g_T2ch, nullptr, nullptr,  g_Z2h[3], 0}; break;  // Z42
        case 4: j = {g_Z1h[0], g_T2ch, g_Z1f[0], nullptr, g_Z3h[0], 1}; break; // Z13
        case 5: j = {g_Z2h[0], g_T2ch, g_Y32[0], nullptr, g_Z4h[0], 1}; break; // Z14
        case 6: j = {g_Z1h[1], g_T2ch, g_Z1f[1], nullptr, g_Z3h[1], 1}; break; // Z23
        case 7: j = {g_Z2h[1], g_T2ch, g_Y32[1], nullptr, g_Z4h[1], 1}; break; // Z24
        }
    } else { // lid == 5
        switch (z) {
        case 0: j = {g_Z1h[2], g_T2ch, g_Z1f[2], nullptr, g_Z3h[2], 1}; break; // Z33
        case 1: j = {g_Z2h[2], g_T2ch, g_Y32[2], nullptr, g_Z4h[2], 1}; break; // Z34
        case 2: j = {g_Z1h[3], g_T2ch, g_Z1f[3], nullptr, g_Z3h[3], 1}; break; // Z43
        case 3: j = {g_Z2h[3], g_T2ch, g_Y32[3], nullptr, g_Z4h[3], 1}; break; // Z44
        }
    }
    return j;
}

// generic batched GEMM kernel (CTA 128x256)
__global__ void __launch_bounds__(256, 1)
k_batch(int lid, const float* __restrict__ x)
{
    const Job jb = get_job(lid, blockIdx.z, x);
    float acc[4][8][4] = {};
    gemm_main1(jb.A, jb.B, acc);

    const int tid = threadIdx.x, lane = tid & 31, wid = tid >> 5;
    const int wm = (wid & 1) * 64, wn = (wid >> 1) * 64;
    const int bm = blockIdx.y * 128, bn = blockIdx.x * 256;
    const int l4 = lane >> 2, l2 = (lane & 3) * 2;
#pragma unroll
    for (int mt = 0; mt < 4; ++mt)
#pragma unroll
        for (int h = 0; h < 2; ++h) {
            const int row = bm + wm + mt * 16 + l4 + h * 8;
#pragma unroll
            for (int nt = 0; nt < 8; ++nt) {
                const int col = bn + wn + nt * 8 + l2;
                const size_t off = (size_t)row * NM + col;
                float vx = acc[mt][nt][2 * h];
                float vy = acc[mt][nt][2 * h + 1];
                if (jb.dmode == 1) {
                    float2 d = *(const float2*)(jb.D + off);
                    vx = 2.f * vx - d.x;
                    vy = 2.f * vy - d.y;
                } else if (jb.dmode == 2) {
                    vx = 2.f * vx - (row == col ? 1.f : 0.f);
                    vy = 2.f * vy - (row == col + 1 ? 1.f : 0.f);
                }
                if (jb.C) *(float2*)(jb.C + off) = make_float2(vx, vy);
                if (jb.H) {
                    __half2 q;
                    q.x = __float2half_rn(vx);
                    q.y = __float2half_rn(vy);
                    *(__half2*)(jb.H + off) = q;
                }
            }
        }
}

// ----------------------------------------------------------------------------
// fp32 -> fp16 conversions
__global__ void __launch_bounds__(256)
k_cvt(const float* __restrict__ x, const float* __restrict__ Lr,
      const float* __restrict__ Lc)
{
    const int zz = blockIdx.z;
    const float* s = (zz == 0) ? x : (zz == 1) ? Lr : Lc;
    __half* H = (zz == 0) ? g_Xh : (zz == 1) ? g_Lrh : g_Lch;
    const int i = (blockIdx.x * 256 + threadIdx.x) * 4;
    float4 v = *(const float4*)(s + i);
    __half2 p;
    p.x = __float2half_rn(v.x); p.y = __float2half_rn(v.y);
    *(__half2*)(H + i) = p;
    p.x = __float2half_rn(v.z); p.y = __float2half_rn(v.w);
    *(__half2*)(H + i + 2) = p;
}

// transpose fp32 source -> fp16 dest (which: 0 = X->XTh, 1 = Y1, 2 = Y2)
__global__ void __launch_bounds__(256)
k_tr(const float* __restrict__ X, int which)
{
    const float* S = (which == 0) ? X : g_Y32[which - 1];
    __half* TH = (which == 0) ? g_XTh : g_YTh[which - 1];
    __shared__ float t[32][33];
    const int tx = threadIdx.x, ty = threadIdx.y;
    const int n0 = blockIdx.x * 32, m0 = blockIdx.y * 32;
#pragma unroll
    for (int i = 0; i < 4; ++i)
        t[ty + 8 * i][tx] = S[(size_t)(m0 + ty + 8 * i) * NM + n0 + tx];
    __syncthreads();
#pragma unroll
    for (int i = 0; i < 4; ++i) {
        const int nl = ty + 8 * i;
        TH[(size_t)(n0 + nl) * NM + m0 + tx] = __float2half_rn(t[tx][nl]);
    }
}

// ----------------------------------------------------------------------------
// Final mix: fp16 plane reads (x stays fp32)
__global__ void __launch_bounds__(256)
k_mix(const float* __restrict__ x, const float* __restrict__ theta,
      const float* __restrict__ bias, float* __restrict__ out)
{
    __shared__ float sh_th[25 * OUTC];
    __shared__ float sh_b[OUTC];
    const int tid = threadIdx.x;
    for (int t = tid; t < 25 * OUTC; t += 256) sh_th[t] = theta[t];
    if (tid < OUTC) sh_b[tid] = bias[tid];
    __syncthreads();

    const int off = (blockIdx.x * 256 + tid) * 2;

    auto ldh = [&](const __half* p) {
        __half2 h = *(const __half2*)(p + off);
        return make_float2(__half2float(h.x), __half2float(h.y));
    };

    float2 v[25];
    v[0] = *(const float2*)(x + off);
#pragma unroll
    for (int j = 1; j <= 4; ++j) v[j] = ldh(g_Wh[j - 1]);
#pragma unroll
    for (int i = 1; i <= 4; ++i) v[i * 5] = ldh(g_Yh[i - 1]);
#pragma unroll
    for (int i = 1; i <= 4; ++i) {
        v[i * 5 + 1] = ldh(g_Z1h[i - 1]);
        v[i * 5 + 2] = ldh(g_Z2h[i - 1]);
        v[i * 5 + 3] = ldh(g_Z3h[i - 1]);
        v[i * 5 + 4] = ldh(g_Z4h[i - 1]);
    }

#pragma unroll
    for (int o = 0; o < OUTC; ++o) {
        float sx = sh_b[o], sy = sh_b[o];
#pragma unroll
        for (int t = 0; t < 25; ++t) {
            const float w = sh_th[t * OUTC + o];
            sx += w * v[t].x;
            sy += w * v[t].y;
        }
        *(float2*)(out + (size_t)o * N2 + off) = make_float2(sx, sy);
    }
}

// ----------------------------------------------------------------------------
extern "C" void kernel_launch(void* const* d_in, const int* in_sizes, int n_in,
                              void* d_out, int out_size)
{
    const float* x     = (const float*)d_in[0];
    const float* Lr    = (const float*)d_in[1];
    const float* Lc    = (const float*)d_in[2];
    const float* theta = (const float*)d_in[3];
    const float* bias  = (const float*)d_in[4];
    float* out = (float*)d_out;

    cudaFuncSetAttribute(k_batch, cudaFuncAttributeMaxDynamicSharedMemorySize, SMEM_DYN);

    const dim3 blk(256);
    const dim3 blkT(32, 8);
    const dim3 gT(NM / 32, NM / 32, 1);

    // conversions
    k_cvt<<<dim3(N2 / 1024, 1, 3), 256>>>(x, Lr, Lc);
    k_tr<<<gT, blkT>>>(x, 0);                              // X^T

    // L1: T2r, T2c, Y1, W1
    k_batch<<<dim3(6, 12, 4), blk, SMEM_DYN>>>(1, x);
    k_tr<<<gT, blkT>>>(x, 1);                              // Y1^T
    // L2: Y2, W2, Y3, W3
    k_batch<<<dim3(6, 12, 4), blk, SMEM_DYN>>>(2, x);
    k_tr<<<gT, blkT>>>(x, 2);                              // Y2^T
    // L3: Y4, W4, Z11, Z12, Z21, Z22
    k_batch<<<dim3(6, 12, 6), blk, SMEM_DYN>>>(3, x);
    // L4: Z31, Z32, Z41, Z42, Z13, Z14, Z23, Z24
    k_batch<<<dim3(6, 12, 8), blk, SMEM_DYN>>>(4, x);
    // L5: Z33, Z34, Z43, Z44
    k_batch<<<dim3(6, 12, 4), blk, SMEM_DYN>>>(5, x);

    // final mix
    k_mix<<<N2 / 512, 256>>>(x, theta, bias, out);
}